// round 1
// baseline (speedup 1.0000x reference)
#include <cuda_runtime.h>
#include <float.h>

// ROI max pool: features [B=2, C=256, H=50, W=50] f32, cat_rois [N=128, 5]
// out [N, C, 7, 7] f32.
// Matches jnp.round (round-half-even) via rintf; STRIDE=16 -> *0.0625f exact.

#define OUTP 7
#define CCH  256
#define HH   50
#define WW   50

__global__ void roi_pool_kernel(const float* __restrict__ feat,
                                const float* __restrict__ rois,
                                float* __restrict__ out,
                                int total)
{
    int t = blockIdx.x * blockDim.x + threadIdx.x;
    if (t >= total) return;

    int j = t % OUTP;
    int i = (t / OUTP) % OUTP;
    int c = (t / (OUTP * OUTP)) % CCH;
    int n = t / (OUTP * OUTP * CCH);

    const float* r = rois + n * 5;
    int im = (int)rintf(r[0]);
    int x1 = (int)rintf(r[1] * 0.0625f);
    int y1 = (int)rintf(r[2] * 0.0625f);
    int x2 = (int)rintf(r[3] * 0.0625f);
    int y2 = (int)rintf(r[4] * 0.0625f);

    int h = y2 - y1 + 1;
    int w = x2 - x1 + 1;

    int ys = i * h / OUTP + y1;
    int ye = ((i + 1) * h + OUTP - 1) / OUTP + y1;
    int xs = j * w / OUTP + x1;
    int xe = ((j + 1) * w + OUTP - 1) / OUTP + x1;

    // Reference masks rows/cols to [0,H)x[0,W); clamp to match.
    ys = max(ys, 0);  xs = max(xs, 0);
    ye = min(ye, HH); xe = min(xe, WW);

    const float* base = feat + ((size_t)im * CCH + c) * (HH * WW);

    float acc = -FLT_MAX;
    for (int y = ys; y < ye; ++y) {
        const float* row = base + y * WW;
        for (int x = xs; x < xe; ++x) {
            acc = fmaxf(acc, __ldg(row + x));
        }
    }
    out[t] = acc;
}

extern "C" void kernel_launch(void* const* d_in, const int* in_sizes, int n_in,
                              void* d_out, int out_size)
{
    const float* feat = (const float*)d_in[0];
    const float* rois = (const float*)d_in[1];
    float* out = (float*)d_out;

    int total = out_size;  // 128*256*7*7 = 1605632
    int threads = 256;
    int blocks = (total + threads - 1) / threads;
    roi_pool_kernel<<<blocks, threads>>>(feat, rois, out, total);
}